// round 2
// baseline (speedup 1.0000x reference)
#include <cuda_runtime.h>
#include <math.h>

// Problem constants
#define BDIM 16384
#define IDIM 512
#define ODIM 256
#define GFEAT 15                 // 1 silu + 8 spline + 6 fractal
#define KDIM (IDIM * GFEAT)      // 7680
#define HH 0.4f                  // grid step (fp32 of 2/5)

// Scratch (device globals: allocation-free rule)
__device__ float g_phi[(size_t)BDIM * KDIM];   // 503 MB feature matrix (B, K)
__device__ float g_w[KDIM * ODIM];             // packed weights (K, O)
__device__ float g_d[IDIM * 5];                // contraction factors

// ---------------------------------------------------------------------------
// d = 0.99 * tanh(d_raw)
// ---------------------------------------------------------------------------
__global__ void k_dfactor(const float* __restrict__ d_raw) {
    int j = blockIdx.x * blockDim.x + threadIdx.x;
    if (j < IDIM * 5) g_d[j] = 0.99f * tanhf(d_raw[j]);
}

// ---------------------------------------------------------------------------
// Pack W[k][o], k = i*15 + g
// ---------------------------------------------------------------------------
__global__ void k_pack(const float* __restrict__ bw,
                       const float* __restrict__ sw,
                       const float* __restrict__ sc,
                       const float* __restrict__ fw) {
    int t = blockIdx.x * blockDim.x + threadIdx.x;
    if (t >= ODIM * IDIM) return;
    int o = t & (ODIM - 1);
    int i = t >> 8;
    int oi = o * IDIM + i;
    float scaler = sc[oi];
    g_w[(size_t)(i * GFEAT + 0) * ODIM + o] = bw[oi];
#pragma unroll
    for (int gs = 0; gs < 8; gs++)
        g_w[(size_t)(i * GFEAT + 1 + gs) * ODIM + o] = sw[(size_t)oi * 8 + gs] * scaler;
#pragma unroll
    for (int gf = 0; gf < 6; gf++)
        g_w[(size_t)(i * GFEAT + 9 + gf) * ODIM + o] = fw[(size_t)oi * 6 + gf];
}

// ---------------------------------------------------------------------------
// Basis features: one thread per (b, i)
// ---------------------------------------------------------------------------
__global__ void k_basis(const float* __restrict__ x) {
    int tid = blockIdx.x * blockDim.x + threadIdx.x;
    if (tid >= BDIM * IDIM) return;
    int i = tid & (IDIM - 1);
    int b = tid >> 9;

    float xv = x[tid];
    float out[GFEAT];

    // --- silu ---
    out[0] = xv / (1.0f + __expf(-xv));

    // --- cubic B-splines, uniform grid, de Boor (unrolled) ---
    float bb[11];
#pragma unroll
    for (int j = 0; j < 11; j++) {
        float gj  = -1.0f + HH * (float)(j - 3);
        float gj1 = -1.0f + HH * (float)(j - 2);
        bb[j] = (xv >= gj && xv < gj1) ? 1.0f : 0.0f;
    }
#pragma unroll
    for (int k = 1; k <= 3; k++) {
        float inv = 1.0f / (HH * (float)k);
#pragma unroll
        for (int j = 0; j < 11; j++) {
            if (j <= 10 - k) {
                float gj   = -1.0f + HH * (float)(j - 3);
                float gjk1 = -1.0f + HH * (float)(j + k + 1 - 3);
                bb[j] = (xv - gj) * inv * bb[j] + (gjk1 - xv) * inv * bb[j + 1];
            }
        }
    }
#pragma unroll
    for (int g = 0; g < 8; g++) out[1 + g] = bb[g];

    // --- fractal hat bases, depth 8 IFS recursion ---
    const float INVH = 2.5f;  // 1/0.4 exact in fp32
    float d0 = g_d[i * 5 + 0], d1 = g_d[i * 5 + 1], d2 = g_d[i * 5 + 2],
          d3 = g_d[i * 5 + 3], d4 = g_d[i * 5 + 4];

    float t = fminf(fmaxf(xv, -1.0f), 1.0f);
    float phi[6];
#pragma unroll
    for (int m = 0; m < 6; m++) {
        float node = -1.0f + HH * (float)m;
        phi[m] = fmaxf(0.0f, 1.0f - fabsf(t - node) * INVH);
    }
    float mult = 1.0f;
#pragma unroll
    for (int dep = 0; dep < 8; dep++) {
        // exact division here: floor is discontinuous, must match reference rounding
        int idx = (int)floorf((t + 1.0f) / HH);
        idx = max(0, min(idx, 4));
        float dv = (idx == 0) ? d0 : (idx == 1) ? d1 : (idx == 2) ? d2
                 : (idx == 3) ? d3 : d4;
        mult *= dv;
        // exact division: t feeds future floors
        float a = t - (-1.0f + (float)idx * HH);
        t = a / HH * 2.0f - 1.0f;
        float u = (t + 1.0f) * 0.5f;
#pragma unroll
        for (int m = 0; m < 6; m++) {
            float node = -1.0f + HH * (float)m;
            float hatv = fmaxf(0.0f, 1.0f - fabsf(t - node) * INVH);
            float basev = (m == 0) ? (1.0f - u) : ((m == 5) ? u : 0.0f);
            phi[m] += mult * (hatv - basev);
        }
    }
#pragma unroll
    for (int m = 0; m < 6; m++) out[9 + m] = phi[m];

    float* dst = g_phi + (size_t)b * KDIM + (size_t)i * GFEAT;
#pragma unroll
    for (int g = 0; g < GFEAT; g++) dst[g] = out[g];
}

// ---------------------------------------------------------------------------
// fp32 SIMT GEMM: out(B,O) = Phi(B,K) * W(K,O). 128x128x16 tile, 8x8/thread.
// ---------------------------------------------------------------------------
#define BM 128
#define BN 128
#define BK 16
#define TM 8
#define TN 8

__global__ void __launch_bounds__(256) k_gemm(float* __restrict__ out) {
    __shared__ float As[BK][BM];   // transposed A tile
    __shared__ float Bs[BK][BN];

    int tid = threadIdx.x;
    int bm = blockIdx.x * BM;
    int bn = blockIdx.y * BN;
    int tx = tid & 15;
    int ty = tid >> 4;
    int m0 = ty * TM;
    int n0 = tx * TN;

    const float* Aptr = g_phi + (size_t)bm * KDIM;
    const float* Bptr = g_w + bn;

    float acc[TM][TN];
#pragma unroll
    for (int mm = 0; mm < TM; mm++)
#pragma unroll
        for (int nn = 0; nn < TN; nn++) acc[mm][nn] = 0.0f;

    for (int kt = 0; kt < KDIM; kt += BK) {
        // A: 128 rows x 16 cols = 512 float4; transpose-store to As[k][m]
#pragma unroll
        for (int r = 0; r < 2; r++) {
            int f = tid + r * 256;
            int m = f >> 2;
            int kq = (f & 3) * 4;
            float4 v = *(const float4*)(Aptr + (size_t)m * KDIM + kt + kq);
            As[kq + 0][m] = v.x;
            As[kq + 1][m] = v.y;
            As[kq + 2][m] = v.z;
            As[kq + 3][m] = v.w;
        }
        // B: 16 rows x 128 cols = 512 float4, direct
#pragma unroll
        for (int r = 0; r < 2; r++) {
            int f = tid + r * 256;
            int kr = f >> 5;
            int c4 = (f & 31) * 4;
            float4 v = *(const float4*)(Bptr + (size_t)(kt + kr) * ODIM + c4);
            *(float4*)&Bs[kr][c4] = v;
        }
        __syncthreads();

#pragma unroll
        for (int k = 0; k < BK; k++) {
            float a[TM], bv[TN];
            *(float4*)&a[0] = *(const float4*)&As[k][m0];
            *(float4*)&a[4] = *(const float4*)&As[k][m0 + 4];
            *(float4*)&bv[0] = *(const float4*)&Bs[k][n0];
            *(float4*)&bv[4] = *(const float4*)&Bs[k][n0 + 4];
#pragma unroll
            for (int mm = 0; mm < TM; mm++)
#pragma unroll
                for (int nn = 0; nn < TN; nn++)
                    acc[mm][nn] = fmaf(a[mm], bv[nn], acc[mm][nn]);
        }
        __syncthreads();
    }

#pragma unroll
    for (int mm = 0; mm < TM; mm++) {
#pragma unroll
        for (int nn = 0; nn < TN; nn += 4) {
            float4 v = make_float4(acc[mm][nn], acc[mm][nn + 1],
                                   acc[mm][nn + 2], acc[mm][nn + 3]);
            *(float4*)(out + (size_t)(bm + m0 + mm) * ODIM + bn + n0 + nn) = v;
        }
    }
}

// ---------------------------------------------------------------------------
extern "C" void kernel_launch(void* const* d_in, const int* in_sizes, int n_in,
                              void* d_out, int out_size) {
    const float* x   = (const float*)d_in[0];
    const float* bw  = (const float*)d_in[1];
    const float* sw  = (const float*)d_in[2];
    const float* sc  = (const float*)d_in[3];
    const float* fw  = (const float*)d_in[4];
    const float* dr  = (const float*)d_in[5];
    float* out = (float*)d_out;

    k_dfactor<<<(IDIM * 5 + 255) / 256, 256>>>(dr);
    k_pack<<<(ODIM * IDIM + 255) / 256, 256>>>(bw, sw, sc, fw);
    k_basis<<<(BDIM * IDIM) / 256, 256>>>(x);
    dim3 grid(BDIM / BM, ODIM / BN);
    k_gemm<<<grid, 256>>>(out);
}

// round 4
// speedup vs baseline: 1.1199x; 1.1199x over previous
#include <cuda_runtime.h>
#include <cuda_bf16.h>
#include <cstdint>
#include <math.h>

// Problem constants
#define BDIM 16384
#define IDIM 512
#define ODIM 256
#define GFEAT 15
#define KDIM (IDIM * GFEAT)   // 7680
#define HH 0.4f

// Scratch (device globals, 16B-aligned for cp.async / float4)
__device__ __align__(16) __nv_bfloat16 g_phi_hi[(size_t)BDIM * KDIM];
__device__ __align__(16) __nv_bfloat16 g_phi_lo[(size_t)BDIM * KDIM];
__device__ __align__(16) __nv_bfloat16 g_wt_hi[(size_t)ODIM * KDIM];   // (O, K)
__device__ __align__(16) __nv_bfloat16 g_wt_lo[(size_t)ODIM * KDIM];
__device__ float g_d[IDIM * 5];

__device__ __forceinline__ void bsplit(float v, __nv_bfloat16& h, __nv_bfloat16& l) {
    h = __float2bfloat16(v);
    l = __float2bfloat16(v - __bfloat162float(h));
}

// ---------------------------------------------------------------------------
__global__ void k_dfactor(const float* __restrict__ d_raw) {
    int j = blockIdx.x * blockDim.x + threadIdx.x;
    if (j < IDIM * 5) g_d[j] = 0.99f * tanhf(d_raw[j]);
}

// ---------------------------------------------------------------------------
// Pack W^T (O, K) in split bf16.  k = i*15 + g
// ---------------------------------------------------------------------------
__global__ void k_pack(const float* __restrict__ bw,
                       const float* __restrict__ sw,
                       const float* __restrict__ sc,
                       const float* __restrict__ fw) {
    int t = blockIdx.x * blockDim.x + threadIdx.x;
    if (t >= ODIM * IDIM) return;
    int i = t & (IDIM - 1);
    int o = t >> 9;
    int oi = o * IDIM + i;
    float scaler = sc[oi];
    float v[GFEAT];
    v[0] = bw[oi];
#pragma unroll
    for (int gs = 0; gs < 8; gs++) v[1 + gs] = sw[(size_t)oi * 8 + gs] * scaler;
#pragma unroll
    for (int gf = 0; gf < 6; gf++) v[9 + gf] = fw[(size_t)oi * 6 + gf];
    size_t base = (size_t)o * KDIM + i * GFEAT;
#pragma unroll
    for (int g = 0; g < GFEAT; g++) {
        __nv_bfloat16 h, l;
        bsplit(v[g], h, l);
        g_wt_hi[base + g] = h;
        g_wt_lo[base + g] = l;
    }
}

// ---------------------------------------------------------------------------
// Basis features (fp32 math, split-bf16 output): one thread per (b, i)
// ---------------------------------------------------------------------------
__global__ void k_basis(const float* __restrict__ x) {
    int tid = blockIdx.x * blockDim.x + threadIdx.x;
    if (tid >= BDIM * IDIM) return;
    int i = tid & (IDIM - 1);
    int b = tid >> 9;

    float xv = x[tid];
    float out[GFEAT];

    // silu
    out[0] = xv / (1.0f + __expf(-xv));

    // cubic B-splines (de Boor, unrolled)
    float bb[11];
#pragma unroll
    for (int j = 0; j < 11; j++) {
        float gj  = -1.0f + HH * (float)(j - 3);
        float gj1 = -1.0f + HH * (float)(j - 2);
        bb[j] = (xv >= gj && xv < gj1) ? 1.0f : 0.0f;
    }
#pragma unroll
    for (int k = 1; k <= 3; k++) {
        float inv = 1.0f / (HH * (float)k);
#pragma unroll
        for (int j = 0; j < 11; j++) {
            if (j <= 10 - k) {
                float gj   = -1.0f + HH * (float)(j - 3);
                float gjk1 = -1.0f + HH * (float)(j + k + 1 - 3);
                bb[j] = (xv - gj) * inv * bb[j] + (gjk1 - xv) * inv * bb[j + 1];
            }
        }
    }
#pragma unroll
    for (int g = 0; g < 8; g++) out[1 + g] = bb[g];

    // fractal bases, depth-8 IFS
    const float INVH = 2.5f;
    float d0 = g_d[i * 5 + 0], d1 = g_d[i * 5 + 1], d2 = g_d[i * 5 + 2],
          d3 = g_d[i * 5 + 3], d4 = g_d[i * 5 + 4];

    float t = fminf(fmaxf(xv, -1.0f), 1.0f);
    float phi[6];
#pragma unroll
    for (int m = 0; m < 6; m++) {
        float node = -1.0f + HH * (float)m;
        phi[m] = fmaxf(0.0f, 1.0f - fabsf(t - node) * INVH);
    }
    float mult = 1.0f;
#pragma unroll
    for (int dep = 0; dep < 8; dep++) {
        int idx = (int)floorf((t + 1.0f) / HH);   // exact div: discontinuous
        idx = max(0, min(idx, 4));
        float dv = (idx == 0) ? d0 : (idx == 1) ? d1 : (idx == 2) ? d2
                 : (idx == 3) ? d3 : d4;
        mult *= dv;
        float a = t - (-1.0f + (float)idx * HH);
        t = a / HH * 2.0f - 1.0f;                 // exact div: feeds floor
        float u = (t + 1.0f) * 0.5f;
#pragma unroll
        for (int m = 0; m < 6; m++) {
            float node = -1.0f + HH * (float)m;
            float hatv = fmaxf(0.0f, 1.0f - fabsf(t - node) * INVH);
            float basev = (m == 0) ? (1.0f - u) : ((m == 5) ? u : 0.0f);
            phi[m] += mult * (hatv - basev);
        }
    }
#pragma unroll
    for (int m = 0; m < 6; m++) out[9 + m] = phi[m];

    size_t base = (size_t)b * KDIM + (size_t)i * GFEAT;
#pragma unroll
    for (int g = 0; g < GFEAT; g++) {
        __nv_bfloat16 h, l;
        bsplit(out[g], h, l);
        g_phi_hi[base + g] = h;
        g_phi_lo[base + g] = l;
    }
}

// ---------------------------------------------------------------------------
// Split-bf16 tensor-core GEMM: out(B,O) = Phi(B,K) @ W(K,O)
//   acc += Ah*Bh + Ah*Bl + Al*Bh   (fp32 accum, mma.sync m16n8k16)
// ---------------------------------------------------------------------------
#define BM 128
#define BN 128
#define BK 32
#define NK (KDIM / BK)        // 240
#define STAGES 3
#define SSTRIDE 40            // bf16 elems per smem row (pad: conflict-free)
#define BUFE (128 * SSTRIDE)  // 5120 elems per buffer
#define STAGEE (4 * BUFE)     // Ah, Al, Bh, Bl
#define SMEM_BYTES (STAGES * STAGEE * 2)   // 122880

__device__ __forceinline__ void cpa16(void* s, const void* g) {
    asm volatile("cp.async.cg.shared.global [%0], [%1], 16;\n"
                 :: "r"((unsigned int)__cvta_generic_to_shared(s)), "l"(g) : "memory");
}
#define CP_COMMIT() asm volatile("cp.async.commit_group;\n" ::: "memory")
#define CP_WAIT1()  asm volatile("cp.async.wait_group 1;\n" ::: "memory")

#define MMA16816(d, a, b)                                                  \
    asm volatile("mma.sync.aligned.m16n8k16.row.col.f32.bf16.bf16.f32 "    \
                 "{%0,%1,%2,%3}, {%4,%5,%6,%7}, {%8,%9}, {%0,%1,%2,%3};"   \
                 : "+f"(d[0]), "+f"(d[1]), "+f"(d[2]), "+f"(d[3])          \
                 : "r"(a[0]), "r"(a[1]), "r"(a[2]), "r"(a[3]),             \
                   "r"(b[0]), "r"(b[1]))

__global__ void __launch_bounds__(256) k_gemm(float* __restrict__ out) {
    extern __shared__ __nv_bfloat16 sm[];

    const int tid  = threadIdx.x;
    const int lane = tid & 31;
    const int warp = tid >> 5;
    const int bm = blockIdx.x * BM;
    const int bn = blockIdx.y * BN;
    const int wm = (warp & 1) * 64;   // warp tile 64x32, 2x4 warp grid
    const int wn = (warp >> 1) * 32;
    const int lr = lane >> 2;   // 0..7
    const int lc = lane & 3;    // 0..3

    // stage loader: 16B chunks, row = c/4, kchunk = c%4
    auto load_stage = [&](int kt, int s) {
        __nv_bfloat16* st = sm + s * STAGEE;
#pragma unroll
        for (int r = 0; r < 2; r++) {
            int c = tid + r * 256;
            int row = c >> 2, kc = c & 3;
            int so = row * SSTRIDE + kc * 8;
            size_t ga = (size_t)(bm + row) * KDIM + kt + kc * 8;
            size_t gb = (size_t)(bn + row) * KDIM + kt + kc * 8;
            cpa16(st + 0 * BUFE + so, g_phi_hi + ga);
            cpa16(st + 1 * BUFE + so, g_phi_lo + ga);
            cpa16(st + 2 * BUFE + so, g_wt_hi + gb);
            cpa16(st + 3 * BUFE + so, g_wt_lo + gb);
        }
        CP_COMMIT();
    };

    float acc[4][4][4];
#pragma unroll
    for (int mm = 0; mm < 4; mm++)
#pragma unroll
        for (int nn = 0; nn < 4; nn++)
#pragma unroll
            for (int q = 0; q < 4; q++) acc[mm][nn][q] = 0.0f;

    load_stage(0, 0);
    load_stage(BK, 1);

    for (int ks = 0; ks < NK; ks++) {
        CP_WAIT1();
        __syncthreads();

        // prefetch ks+2 (stage being overwritten was consumed at ks-1)
        if (ks + 2 < NK) load_stage((ks + 2) * BK, (ks + 2) % STAGES);
        else CP_COMMIT();   // keep group accounting aligned

        const __nv_bfloat16* Ah = sm + (ks % STAGES) * STAGEE;
        const __nv_bfloat16* Al = Ah + BUFE;
        const __nv_bfloat16* Bh = Ah + 2 * BUFE;
        const __nv_bfloat16* Bl = Ah + 3 * BUFE;

#pragma unroll
        for (int kk = 0; kk < BK; kk += 16) {
            uint32_t ah[4][4], al[4][4], bh[4][2], bl[4][2];
#pragma unroll
            for (int mm = 0; mm < 4; mm++) {
                int base = (wm + mm * 16 + lr) * SSTRIDE + kk + 2 * lc;
                ah[mm][0] = *(const uint32_t*)(Ah + base);
                ah[mm][1] = *(const uint32_t*)(Ah + base + 8 * SSTRIDE);
                ah[mm][2] = *(const uint32_t*)(Ah + base + 8);
                ah[mm][3] = *(const uint32_t*)(Ah + base + 8 * SSTRIDE + 8);
                al[mm][0] = *(const uint32_t*)(Al + base);
                al[mm][1] = *(const uint32_t*)(Al + base + 8 * SSTRIDE);
                al[mm][2] = *(const uint32_t*)(Al + base + 8);
                al[mm][3] = *(const uint32_t*)(Al + base + 8 * SSTRIDE + 8);
            }
#pragma unroll
            for (int nn = 0; nn < 4; nn++) {
                int base = (wn + nn * 8 + lr) * SSTRIDE + kk + 2 * lc;
                bh[nn][0] = *(const uint32_t*)(Bh + base);
                bh[nn][1] = *(const uint32_t*)(Bh + base + 8);
                bl[nn][0] = *(const uint32_t*)(Bl + base);
                bl[nn][1] = *(const uint32_t*)(Bl + base + 8);
            }
#pragma unroll
            for (int mm = 0; mm < 4; mm++)
#pragma unroll
                for (int nn = 0; nn < 4; nn++) {
                    MMA16816(acc[mm][nn], ah[mm], bh[nn]);
                    MMA16816(acc[mm][nn], ah[mm], bl[nn]);
                    MMA16816(acc[mm][nn], al[mm], bh[nn]);
                }
        }
        __syncthreads();
    }

    // epilogue
#pragma unroll
    for (int mm = 0; mm < 4; mm++) {
#pragma unroll
        for (int nn = 0; nn < 4; nn++) {
            int row = bm + wm + mm * 16 + lr;
            int col = bn + wn + nn * 8 + 2 * lc;
            float2 v0 = make_float2(acc[mm][nn][0], acc[mm][nn][1]);
            float2 v1 = make_float2(acc[mm][nn][2], acc[mm][nn][3]);
            *(float2*)(out + (size_t)row * ODIM + col) = v0;
            *(float2*)(out + (size_t)(row + 8) * ODIM + col) = v1;
        }
    }
}

// ---------------------------------------------------------------------------
extern "C" void kernel_launch(void* const* d_in, const int* in_sizes, int n_in,
                              void* d_out, int out_size) {
    const float* x  = (const float*)d_in[0];
    const float* bw = (const float*)d_in[1];
    const float* sw = (const float*)d_in[2];
    const float* sc = (const float*)d_in[3];
    const float* fw = (const float*)d_in[4];
    const float* dr = (const float*)d_in[5];
    float* out = (float*)d_out;

    cudaFuncSetAttribute(k_gemm, cudaFuncAttributeMaxDynamicSharedMemorySize,
                         SMEM_BYTES);

    k_dfactor<<<(IDIM * 5 + 255) / 256, 256>>>(dr);
    k_pack<<<(ODIM * IDIM + 255) / 256, 256>>>(bw, sw, sc, fw);
    k_basis<<<(BDIM * IDIM) / 256, 256>>>(x);
    dim3 grid(BDIM / BM, ODIM / BN);
    k_gemm<<<grid, 256, SMEM_BYTES>>>(out);
}

// round 5
// speedup vs baseline: 1.9720x; 1.7609x over previous
#include <cuda_runtime.h>
#include <cuda_bf16.h>
#include <cstdint>
#include <math.h>

// Problem constants
#define BDIM 16384
#define IDIM 512
#define ODIM 256
#define GFEAT 15
#define KDIM (IDIM * GFEAT)   // 7680
#define HH 0.4f

// Scratch (device globals, 16B-aligned)
__device__ __align__(16) __nv_bfloat16 g_phi_hi[(size_t)BDIM * KDIM];
__device__ __align__(16) __nv_bfloat16 g_phi_lo[(size_t)BDIM * KDIM];
__device__ __align__(16) __nv_bfloat16 g_wt_hi[(size_t)ODIM * KDIM];   // (O, K)
__device__ __align__(16) __nv_bfloat16 g_wt_lo[(size_t)ODIM * KDIM];
__device__ float g_d[IDIM * 5];

__device__ __forceinline__ void bsplit(float v, __nv_bfloat16& h, __nv_bfloat16& l) {
    h = __float2bfloat16(v);
    l = __float2bfloat16(v - __bfloat162float(h));
}

// ---------------------------------------------------------------------------
__global__ void k_dfactor(const float* __restrict__ d_raw) {
    int j = blockIdx.x * blockDim.x + threadIdx.x;
    if (j < IDIM * 5) g_d[j] = 0.99f * tanhf(d_raw[j]);
}

// ---------------------------------------------------------------------------
// Pack W^T (O, K) in split bf16.  k = i*15 + g
// ---------------------------------------------------------------------------
__global__ void k_pack(const float* __restrict__ bw,
                       const float* __restrict__ sw,
                       const float* __restrict__ sc,
                       const float* __restrict__ fw) {
    int t = blockIdx.x * blockDim.x + threadIdx.x;
    if (t >= ODIM * IDIM) return;
    int i = t & (IDIM - 1);
    int o = t >> 9;
    int oi = o * IDIM + i;
    float scaler = sc[oi];
    float v[GFEAT];
    v[0] = bw[oi];
#pragma unroll
    for (int gs = 0; gs < 8; gs++) v[1 + gs] = sw[(size_t)oi * 8 + gs] * scaler;
#pragma unroll
    for (int gf = 0; gf < 6; gf++) v[9 + gf] = fw[(size_t)oi * 6 + gf];
    size_t base = (size_t)o * KDIM + i * GFEAT;
#pragma unroll
    for (int g = 0; g < GFEAT; g++) {
        __nv_bfloat16 h, l;
        bsplit(v[g], h, l);
        g_wt_hi[base + g] = h;
        g_wt_lo[base + g] = l;
    }
}

// ---------------------------------------------------------------------------
// Basis features: fp32 math, smem-staged coalesced split-bf16 output.
// One thread per (b,i); each 256-thread block covers a contiguous 3840-elem
// span of one Phi row -> fully coalesced uint4 stores.
// ---------------------------------------------------------------------------
__global__ void __launch_bounds__(256) k_basis(const float* __restrict__ x) {
    __shared__ __align__(16) __nv_bfloat16 sh[256 * GFEAT];
    __shared__ __align__(16) __nv_bfloat16 sl[256 * GFEAT];

    const int tid = threadIdx.x;
    const int gid = blockIdx.x * 256 + tid;
    const int i = gid & (IDIM - 1);

    float xv = x[gid];
    float out[GFEAT];

    // silu
    out[0] = xv / (1.0f + __expf(-xv));

    // cubic B-splines (de Boor, unrolled; uniform grid)
    float bb[11];
#pragma unroll
    for (int j = 0; j < 11; j++) {
        float gj  = -1.0f + HH * (float)(j - 3);
        float gj1 = -1.0f + HH * (float)(j - 2);
        bb[j] = (xv >= gj && xv < gj1) ? 1.0f : 0.0f;
    }
#pragma unroll
    for (int k = 1; k <= 3; k++) {
        float inv = 1.0f / (HH * (float)k);
#pragma unroll
        for (int j = 0; j < 11; j++) {
            if (j <= 10 - k) {
                float gj   = -1.0f + HH * (float)(j - 3);
                float gjk1 = -1.0f + HH * (float)(j + k + 1 - 3);
                bb[j] = (xv - gj) * inv * bb[j] + (gjk1 - xv) * inv * bb[j + 1];
            }
        }
    }
#pragma unroll
    for (int g = 0; g < 8; g++) out[1 + g] = bb[g];

    // fractal bases, depth-8 IFS (divisions -> multiplies)
    const float INVH = 2.5f;
    float d0 = g_d[i * 5 + 0], d1 = g_d[i * 5 + 1], d2 = g_d[i * 5 + 2],
          d3 = g_d[i * 5 + 3], d4 = g_d[i * 5 + 4];

    float t = fminf(fmaxf(xv, -1.0f), 1.0f);
    float phi[6];
#pragma unroll
    for (int m = 0; m < 6; m++) {
        float node = -1.0f + HH * (float)m;
        phi[m] = fmaxf(0.0f, 1.0f - fabsf(t - node) * INVH);
    }
    float mult = 1.0f;
#pragma unroll
    for (int dep = 0; dep < 8; dep++) {
        int idx = (int)floorf((t + 1.0f) * INVH);
        idx = max(0, min(idx, 4));
        float dv = (idx == 0) ? d0 : (idx == 1) ? d1 : (idx == 2) ? d2
                 : (idx == 3) ? d3 : d4;
        mult *= dv;
        float a = t - (-1.0f + (float)idx * HH);
        t = a * 5.0f - 1.0f;
        float u = (t + 1.0f) * 0.5f;
#pragma unroll
        for (int m = 0; m < 6; m++) {
            float node = -1.0f + HH * (float)m;
            float hatv = fmaxf(0.0f, 1.0f - fabsf(t - node) * INVH);
            float basev = (m == 0) ? (1.0f - u) : ((m == 5) ? u : 0.0f);
            phi[m] += mult * (hatv - basev);
        }
    }
#pragma unroll
    for (int m = 0; m < 6; m++) out[9 + m] = phi[m];

    // split + stage in smem
#pragma unroll
    for (int g = 0; g < GFEAT; g++) {
        __nv_bfloat16 h, l;
        bsplit(out[g], h, l);
        sh[tid * GFEAT + g] = h;
        sl[tid * GFEAT + g] = l;
    }
    __syncthreads();

    // coalesced copy-out: 3840 bf16 = 480 uint4 per array
    size_t dstbase = (size_t)(blockIdx.x) * (256 * GFEAT);
    uint4* dh = (uint4*)(g_phi_hi + dstbase);
    uint4* dl = (uint4*)(g_phi_lo + dstbase);
    const uint4* svh = (const uint4*)sh;
    const uint4* svl = (const uint4*)sl;
#pragma unroll
    for (int t4 = tid; t4 < 480; t4 += 256) {
        dh[t4] = svh[t4];
        dl[t4] = svl[t4];
    }
}

// ---------------------------------------------------------------------------
// Split-bf16 tensor-core GEMM: out(B,O) = Phi(B,K) @ W(K,O)
//   acc += Ah*Bh + Ah*Bl + Al*Bh   (fp32 accum, mma.sync m16n8k16)
// ---------------------------------------------------------------------------
#define BM 128
#define BN 128
#define BK 32
#define NK (KDIM / BK)        // 240
#define STAGES 2
#define SSTRIDE 40            // bf16/row; 80B stride -> conflict-free ldmatrix
#define BUFE (128 * SSTRIDE)  // 5120 elems per buffer
#define STAGEE (4 * BUFE)     // Ah, Al, Bh, Bl
#define SMEM_BYTES (STAGES * STAGEE * 2)   // 81920

__device__ __forceinline__ void cpa16(void* s, const void* g) {
    asm volatile("cp.async.cg.shared.global [%0], [%1], 16;\n"
                 :: "r"((unsigned int)__cvta_generic_to_shared(s)), "l"(g) : "memory");
}
#define CP_COMMIT() asm volatile("cp.async.commit_group;\n" ::: "memory")
#define CP_WAIT1()  asm volatile("cp.async.wait_group 1;\n" ::: "memory")
#define CP_WAIT0()  asm volatile("cp.async.wait_group 0;\n" ::: "memory")

__device__ __forceinline__ void ldsm4(uint32_t& r0, uint32_t& r1,
                                      uint32_t& r2, uint32_t& r3, const void* p) {
    unsigned a = (unsigned)__cvta_generic_to_shared(p);
    asm volatile("ldmatrix.sync.aligned.m8n8.x4.shared.b16 {%0,%1,%2,%3}, [%4];"
                 : "=r"(r0), "=r"(r1), "=r"(r2), "=r"(r3) : "r"(a));
}
__device__ __forceinline__ void ldsm2(uint32_t& r0, uint32_t& r1, const void* p) {
    unsigned a = (unsigned)__cvta_generic_to_shared(p);
    asm volatile("ldmatrix.sync.aligned.m8n8.x2.shared.b16 {%0,%1}, [%2];"
                 : "=r"(r0), "=r"(r1) : "r"(a));
}

#define MMA16816(d, a, b)                                                  \
    asm volatile("mma.sync.aligned.m16n8k16.row.col.f32.bf16.bf16.f32 "    \
                 "{%0,%1,%2,%3}, {%4,%5,%6,%7}, {%8,%9}, {%0,%1,%2,%3};"   \
                 : "+f"(d[0]), "+f"(d[1]), "+f"(d[2]), "+f"(d[3])          \
                 : "r"(a[0]), "r"(a[1]), "r"(a[2]), "r"(a[3]),             \
                   "r"(b[0]), "r"(b[1]))

__global__ void __launch_bounds__(256, 2) k_gemm(float* __restrict__ out) {
    extern __shared__ __nv_bfloat16 sm[];

    const int tid  = threadIdx.x;
    const int lane = tid & 31;
    const int warp = tid >> 5;
    const int bm = blockIdx.x * BM;
    const int bn = blockIdx.y * BN;
    const int wm = (warp & 1) * 64;   // warp tile 64x32, 2x4 warp grid
    const int wn = (warp >> 1) * 32;
    const int lr = lane >> 2;
    const int lc = lane & 3;

    // ldmatrix per-lane base offsets (elements)
    const int aoff = (wm + (lane & 15)) * SSTRIDE + ((lane >> 4) << 3);
    const int l2   = lane & 15;
    const int boff = (wn + (l2 & 7)) * SSTRIDE + ((l2 >> 3) << 3);

    auto load_stage = [&](int kt, int s) {
        __nv_bfloat16* st = sm + s * STAGEE;
#pragma unroll
        for (int r = 0; r < 2; r++) {
            int c = tid + r * 256;
            int row = c >> 2, kc = c & 3;
            int so = row * SSTRIDE + kc * 8;
            size_t ga = (size_t)(bm + row) * KDIM + kt + kc * 8;
            size_t gb = (size_t)(bn + row) * KDIM + kt + kc * 8;
            cpa16(st + 0 * BUFE + so, g_phi_hi + ga);
            cpa16(st + 1 * BUFE + so, g_phi_lo + ga);
            cpa16(st + 2 * BUFE + so, g_wt_hi + gb);
            cpa16(st + 3 * BUFE + so, g_wt_lo + gb);
        }
        CP_COMMIT();
    };

    float acc[4][4][4];
#pragma unroll
    for (int mm = 0; mm < 4; mm++)
#pragma unroll
        for (int nn = 0; nn < 4; nn++)
#pragma unroll
            for (int q = 0; q < 4; q++) acc[mm][nn][q] = 0.0f;

    load_stage(0, 0);
    load_stage(BK, 1);

    for (int ks = 0; ks < NK; ks++) {
        if (ks + 2 < NK) { CP_WAIT1(); } else { CP_WAIT0(); }
        __syncthreads();

        const __nv_bfloat16* Ah = sm + (ks & 1) * STAGEE;
        const __nv_bfloat16* Al = Ah + BUFE;
        const __nv_bfloat16* Bh = Ah + 2 * BUFE;
        const __nv_bfloat16* Bl = Ah + 3 * BUFE;

#pragma unroll
        for (int kk = 0; kk < BK; kk += 16) {
            uint32_t ah[4][4], al[4][4], bh[4][2], bl[4][2];
#pragma unroll
            for (int mm = 0; mm < 4; mm++) {
                int o = aoff + mm * 16 * SSTRIDE + kk;
                ldsm4(ah[mm][0], ah[mm][1], ah[mm][2], ah[mm][3], Ah + o);
                ldsm4(al[mm][0], al[mm][1], al[mm][2], al[mm][3], Al + o);
            }
#pragma unroll
            for (int nn = 0; nn < 4; nn++) {
                int o = boff + nn * 8 * SSTRIDE + kk;
                ldsm2(bh[nn][0], bh[nn][1], Bh + o);
                ldsm2(bl[nn][0], bl[nn][1], Bl + o);
            }
#pragma unroll
            for (int mm = 0; mm < 4; mm++)
#pragma unroll
                for (int nn = 0; nn < 4; nn++) {
                    MMA16816(acc[mm][nn], ah[mm], bh[nn]);
                    MMA16816(acc[mm][nn], ah[mm], bl[nn]);
                    MMA16816(acc[mm][nn], al[mm], bh[nn]);
                }
        }
        __syncthreads();
        if (ks + 2 < NK) load_stage((ks + 2) * BK, ks & 1);
    }

    // epilogue
#pragma unroll
    for (int mm = 0; mm < 4; mm++) {
#pragma unroll
        for (int nn = 0; nn < 4; nn++) {
            int row = bm + wm + mm * 16 + lr;
            int col = bn + wn + nn * 8 + 2 * lc;
            float2 v0 = make_float2(acc[mm][nn][0], acc[mm][nn][1]);
            float2 v1 = make_float2(acc[mm][nn][2], acc[mm][nn][3]);
            *(float2*)(out + (size_t)row * ODIM + col) = v0;
            *(float2*)(out + (size_t)(row + 8) * ODIM + col) = v1;
        }
    }
}

// ---------------------------------------------------------------------------
extern "C" void kernel_launch(void* const* d_in, const int* in_sizes, int n_in,
                              void* d_out, int out_size) {
    const float* x  = (const float*)d_in[0];
    const float* bw = (const float*)d_in[1];
    const float* sw = (const float*)d_in[2];
    const float* sc = (const float*)d_in[3];
    const float* fw = (const float*)d_in[4];
    const float* dr = (const float*)d_in[5];
    float* out = (float*)d_out;

    cudaFuncSetAttribute(k_gemm, cudaFuncAttributeMaxDynamicSharedMemorySize,
                         SMEM_BYTES);

    k_dfactor<<<(IDIM * 5 + 255) / 256, 256>>>(dr);
    k_pack<<<(ODIM * IDIM + 255) / 256, 256>>>(bw, sw, sc, fw);
    k_basis<<<(BDIM * IDIM) / 256, 256>>>(x);
    dim3 grid(BDIM / BM, ODIM / BN);
    k_gemm<<<grid, 256, SMEM_BYTES>>>(out);
}